// round 16
// baseline (speedup 1.0000x reference)
#include <cuda_runtime.h>
#include <cstdint>
#include <cstddef>

// FlowNetC correlation: out[b, dy*9+dx, y, x] = (1/C) * sum_c in1[b,c,y,x] * in2[b,c,y+dy-4,x+dx-4]
// Shapes fixed: C=256, H=96, W=128, 81 displacement channels.
// R16: occupancy attack. TY=4 tile, 288 threads (warp == dyi), scalar FFMA 4-wide strips
// (the best-measured inner loop), 3 CTAs/SM via __launch_bounds__(288,3).

#define C_CH 256
#define H_IN 96
#define W_IN 128
#define ND   9
#define MD   4
#define TY   4
#define TX   32
#define CK   8
#define SY   (TY + 2*MD)        // 12 haloed rows of in2
#define SX   (TX + 2*MD)        // 40 haloed cols of in2
#define NTHREADS 288            // 9 warps; warp = dyi; lane = (qy 0..3, qx 0..7)
#define S1_FLOATS (CK*TY*TX)    // 1024
#define S2_FLOATS (CK*SY*SX)    // 3840
#define BUF_FLOATS (S1_FLOATS + S2_FLOATS)  // 4864
#define SMEM_BYTES (2*BUF_FLOATS*4)         // 38912/CTA; x3 CTAs = 116.7KB/SM

__device__ __forceinline__ void cp_async16(uint32_t saddr, const float* gsrc, int src_bytes) {
    asm volatile("cp.async.cg.shared.global [%0], [%1], 16, %2;\n"
                 :: "r"(saddr), "l"(gsrc), "r"(src_bytes));
}
__device__ __forceinline__ void cp_commit() {
    asm volatile("cp.async.commit_group;\n" ::: "memory");
}
__device__ __forceinline__ void cp_wait1() {
    asm volatile("cp.async.wait_group 1;\n" ::: "memory");
}

__device__ __forceinline__ void issue_stage(uint32_t smem_base, int buf, int c0,
                                            const float* __restrict__ in1b,
                                            const float* __restrict__ in2b,
                                            int ty0, int tx0, int tid) {
    uint32_t s1a = smem_base + (uint32_t)buf * (BUF_FLOATS * 4);
    uint32_t s2a = s1a + S1_FLOATS * 4;

    // in1 tile: CK x TY x TX. 256 float4s, always in bounds.
    #pragma unroll 1
    for (int i = tid; i < S1_FLOATS / 4; i += NTHREADS) {
        int col4 = i & 7;           // 8 float4 per 32-float row
        int row  = (i >> 3) & 3;    // TY=4
        int cc   = i >> 5;          // CK
        const float* src = in1b + ((size_t)(c0 + cc) * H_IN + (ty0 + row)) * W_IN
                                + tx0 + col4 * 4;
        cp_async16(s1a + (uint32_t)i * 16, src, 16);
    }
    // in2 haloed tile: CK x SY x SX. 960 float4s. OOB float4s are fully in or fully
    // out (W%4==0, MD==4) -> src-size 0 zero-fills.
    #pragma unroll 1
    for (int i = tid; i < S2_FLOATS / 4; i += NTHREADS) {
        int col4 = i % (SX / 4);            // 10 float4 per row
        int row  = (i / (SX / 4)) % SY;     // 12 rows
        int cc   = i / ((SX / 4) * SY);     // CK
        int gx = tx0 + col4 * 4 - MD;
        int gy = ty0 + row - MD;
        bool ok = (gy >= 0) & (gy < H_IN) & (gx >= 0) & (gx <= W_IN - 4);
        const float* src = in2b + ((size_t)(c0 + cc) * H_IN + (ok ? gy : 0)) * W_IN
                                + (ok ? gx : 0);
        cp_async16(s2a + (uint32_t)i * 16, src, ok ? 16 : 0);
    }
}

__global__ void __launch_bounds__(NTHREADS, 3)
Correlation_72164040507827_kernel(const float* __restrict__ in1,
                                  const float* __restrict__ in2,
                                  float* __restrict__ out) {
    extern __shared__ float smem[];
    const int tid = threadIdx.x;
    const int b   = blockIdx.z;
    const int ty0 = blockIdx.y * TY;
    const int tx0 = blockIdx.x * TX;

    const int dyi = tid >> 5;      // warp = one dyi, 0..8
    const int l   = tid & 31;
    const int qy  = l >> 3;        // 0..3 rows
    const int qx  = l & 7;         // 0..7 x-quads (4-wide strip)

    float acc[ND][4];
    #pragma unroll
    for (int d = 0; d < ND; ++d)
        #pragma unroll
        for (int j = 0; j < 4; ++j) acc[d][j] = 0.0f;

    const float* in1b = in1 + (size_t)b * C_CH * (H_IN * W_IN);
    const float* in2b = in2 + (size_t)b * C_CH * (H_IN * W_IN);

    uint32_t smem_base = (uint32_t)__cvta_generic_to_shared(smem);

    issue_stage(smem_base, 0, 0, in1b, in2b, ty0, tx0, tid);
    cp_commit();

    const int s1off = qy * TX + qx * 4;
    const int s2off = (qy + dyi) * SX + qx * 4;

    const int nChunks = C_CH / CK;  // 32
    #pragma unroll 1
    for (int k = 0; k < nChunks; ++k) {
        if (k + 1 < nChunks)
            issue_stage(smem_base, (k + 1) & 1, (k + 1) * CK, in1b, in2b, ty0, tx0, tid);
        cp_commit();            // (possibly empty) group keeps wait_group accounting uniform
        cp_wait1();             // stage k resident
        __syncthreads();

        const float* buf = smem + (size_t)(k & 1) * BUF_FLOATS;
        const float* s1c = buf + s1off;
        const float* s2c = buf + S1_FLOATS + s2off;

        #pragma unroll
        for (int cc = 0; cc < CK; ++cc) {
            float4 a  = *(const float4*)(s1c);
            float4 r0 = *(const float4*)(s2c);
            float4 r1 = *(const float4*)(s2c + 4);
            float4 r2 = *(const float4*)(s2c + 8);
            s1c += TY * TX;
            s2c += SY * SX;
            float r[12] = {r0.x, r0.y, r0.z, r0.w,
                           r1.x, r1.y, r1.z, r1.w,
                           r2.x, r2.y, r2.z, r2.w};
            #pragma unroll
            for (int dx = 0; dx < ND; ++dx) {
                acc[dx][0] += a.x * r[dx + 0];
                acc[dx][1] += a.y * r[dx + 1];
                acc[dx][2] += a.z * r[dx + 2];
                acc[dx][3] += a.w * r[dx + 3];
            }
        }
        __syncthreads();  // buffer (k&1) fully consumed before refill at k+1
    }

    // Epilogue: normalize and store float4 per dx (coalesced within warp).
    const float scale = 1.0f / (float)C_CH;
    const int y = ty0 + qy;
    const int x = tx0 + qx * 4;
    #pragma unroll
    for (int dx = 0; dx < ND; ++dx) {
        float4 v;
        v.x = acc[dx][0] * scale;
        v.y = acc[dx][1] * scale;
        v.z = acc[dx][2] * scale;
        v.w = acc[dx][3] * scale;
        size_t o = (((size_t)b * (ND * ND) + dyi * ND + dx) * H_IN + y) * W_IN + x;
        *(float4*)(out + o) = v;
    }
}

extern "C" void kernel_launch(void* const* d_in, const int* in_sizes, int n_in,
                              void* d_out, int out_size) {
    const float* in1 = (const float*)d_in[0];
    const float* in2 = (const float*)d_in[1];
    float* out = (float*)d_out;

    int B = in_sizes[0] / (C_CH * H_IN * W_IN);

    static bool attr_set = false;
    if (!attr_set) {
        cudaFuncSetAttribute(Correlation_72164040507827_kernel,
                             cudaFuncAttributeMaxDynamicSharedMemorySize, SMEM_BYTES);
        attr_set = true;
    }

    dim3 grid(W_IN / TX, H_IN / TY, B);  // 4 x 24 x B
    Correlation_72164040507827_kernel<<<grid, NTHREADS, SMEM_BYTES>>>(in1, in2, out);
}